// round 4
// baseline (speedup 1.0000x reference)
#include <cuda_runtime.h>
#include <math.h>

#define N_NODES  50000
#define N_EDGES  800000
#define F_DIM    64
#define L_DIM    1024
#define R_ROUNDS 3
#define N_CLASS  10

#define FB_THREADS 384        // 12 warps = 6 node-groups x 2 bin-groups
#define NPW      8            // nodes per warp
#define BINW     512          // bins per warp
#define NPB      48           // nodes per block

// Scratch (device globals — no allocation allowed)
__device__ float g_e[N_NODES * F_DIM];   // current embeddings (r after gemm1)
__device__ float g_v[N_NODES * F_DIM];   // v = e + scatter-sum
__device__ float g_f[L_DIM];             // fingerprint accumulator

__device__ __forceinline__ void red_add_v4(float* p, float4 v) {
    asm volatile("red.global.add.v4.f32 [%0], {%1,%2,%3,%4};"
                 :: "l"(p), "f"(v.x), "f"(v.y), "f"(v.z), "f"(v.w) : "memory");
}
__device__ __forceinline__ unsigned long long pack2(float a, float b) {
    unsigned long long r;
    asm("mov.b64 %0, {%1,%2};" : "=l"(r) : "f"(a), "f"(b));
    return r;
}
__device__ __forceinline__ void unpack2(unsigned long long v, float& a, float& b) {
    asm("mov.b64 {%0,%1}, %2;" : "=f"(a), "=f"(b) : "l"(v));
}
__device__ __forceinline__ void fma2(unsigned long long& d,
                                     unsigned long long a, unsigned long long b) {
    asm("fma.rn.f32x2 %0, %1, %2, %0;" : "+l"(d) : "l"(a), "l"(b));
}
__device__ __forceinline__ void cp_async16(void* smem_dst, const void* gsrc) {
    unsigned sa = (unsigned)__cvta_generic_to_shared(smem_dst);
    asm volatile("cp.async.cg.shared.global [%0], [%1], 16;" :: "r"(sa), "l"(gsrc) : "memory");
}
#define CP_COMMIT() asm volatile("cp.async.commit_group;" ::: "memory")
#define CP_WAIT1()  asm volatile("cp.async.wait_group 1;" ::: "memory")

// e = emb[node_feature]; v = e; f = 0
__global__ void gather_init(const int* __restrict__ nf, const float* __restrict__ emb) {
    int tid = blockIdx.x * blockDim.x + threadIdx.x;
    if (tid < L_DIM) g_f[tid] = 0.0f;
    if (tid >= N_NODES * 16) return;
    int node = tid >> 4;
    int c    = tid & 15;
    int ft = nf[node];
    float4 val = ((const float4*)emb)[ft * 16 + c];
    ((float4*)g_e)[node * 16 + c] = val;
    ((float4*)g_v)[node * 16 + c] = val;
}

// v[dst] += e[src] for every edge (vector atomics, 16 threads/edge)
__global__ void scatter_kernel(const int* __restrict__ src, const int* __restrict__ dst) {
    int tid = blockIdx.x * blockDim.x + threadIdx.x;
    if (tid >= N_EDGES * 16) return;
    int e = tid >> 4;
    int c = tid & 15;
    int s = __ldg(src + e);
    int d = __ldg(dst + e);
    float4 val = ((const float4*)g_e)[s * 16 + c];
    red_add_v4(g_v + d * 64 + c * 4, val);
}

// r = relu(v @ Wh[l] + bh[l]); write r into BOTH g_e and g_v (v-init for next round)
__global__ void __launch_bounds__(256) gemm1_kernel(const float* __restrict__ Wh,
                                                    const float* __restrict__ bh, int l) {
    __shared__ __align__(16) float Whs[F_DIM * F_DIM];
    __shared__ __align__(16) float bhs[F_DIM];
    int t = threadIdx.x;
    {
        const float4* W4 = (const float4*)(Wh + l * F_DIM * F_DIM);
        float4* Ws4 = (float4*)Whs;
        for (int i = t; i < F_DIM * F_DIM / 4; i += 256) Ws4[i] = W4[i];
        if (t < F_DIM) bhs[t] = bh[l * F_DIM + t];
    }
    __syncthreads();
    int node = blockIdx.x * 256 + t;
    if (node >= N_NODES) return;

    unsigned long long acc2[32];
#pragma unroll
    for (int j2 = 0; j2 < 32; j2++) acc2[j2] = ((const unsigned long long*)bhs)[j2];

    const float4* v4 = ((const float4*)g_v) + node * 16;
    const float4* W4 = (const float4*)Whs;
#pragma unroll
    for (int k4 = 0; k4 < 16; k4++) {
        float4 vv = v4[k4];
        float s[4] = {vv.x, vv.y, vv.z, vv.w};
#pragma unroll
        for (int q = 0; q < 4; q++) {
            unsigned long long a = pack2(s[q], s[q]);
            int k = k4 * 4 + q;
#pragma unroll
            for (int j4 = 0; j4 < 16; j4++) {
                float4 wv = W4[k * 16 + j4];
                fma2(acc2[j4 * 2],     a, pack2(wv.x, wv.y));
                fma2(acc2[j4 * 2 + 1], a, pack2(wv.z, wv.w));
            }
        }
    }
    float4* e4 = ((float4*)g_e) + node * 16;
    float4* w4 = ((float4*)g_v) + node * 16;
#pragma unroll
    for (int j4 = 0; j4 < 16; j4++) {
        float a, b, c, d;
        unpack2(acc2[j4 * 2],     a, b);
        unpack2(acc2[j4 * 2 + 1], c, d);
        float4 o;
        o.x = fmaxf(a, 0.0f); o.y = fmaxf(b, 0.0f);
        o.z = fmaxf(c, 0.0f); o.w = fmaxf(d, 0.0f);
        e4[j4] = o;
        w4[j4] = o;
    }
}

// Fused GEMM2 + softmax + fingerprint accumulation.
// 12 warps = 6 node-groups (wi) x 2 bin-groups (wj).
// Warp (wi,wj): 8 nodes x 512 bins. acc[n*8+g*2+h] = bins wj*512+g*128+lane*4+{2h,2h+1}.
// Wo streamed via cp.async double-buffered 8-row chunks; online softmax combine across wj.
__global__ void __launch_bounds__(FB_THREADS, 1)
fused_kernel(const float* __restrict__ Wo, const float* __restrict__ bo, int l) {
    __shared__ __align__(16) float Wos[2][8 * L_DIM];   // 2 x 32 KB
    __shared__ __align__(16) float rs[NPB * F_DIM];     // 12 KB
    __shared__ __align__(16) float fpart[L_DIM];        // 4 KB
    __shared__ float pm[NPB][2];                        // partial max
    __shared__ float ps[NPB][2];                        // partial sumexp

    int t = threadIdx.x;
    int w = t >> 5;
    int lane = t & 31;
    int wj = w & 1;        // bin group
    int wi = w >> 1;       // node group
    int nodeBase = blockIdx.x * NPB + wi * NPW;

    for (int i = t; i < L_DIM; i += FB_THREADS) fpart[i] = 0.0f;
    {
        const float4* e4 = (const float4*)g_e;
        float4* rs4 = (float4*)rs;
        for (int i = t; i < NPB * 16; i += FB_THREADS) {
            int node = blockIdx.x * NPB + (i >> 4);
            if (node < N_NODES) rs4[i] = e4[node * 16 + (i & 15)];
            else                rs4[i] = make_float4(0.f, 0.f, 0.f, 0.f);
        }
    }

    unsigned long long acc[NPW * 8];
    {
        const float4* bo4 = (const float4*)(bo + l * L_DIM);
#pragma unroll
        for (int g = 0; g < 4; g++) {
            float4 b = bo4[wj * 128 + g * 32 + lane];
            unsigned long long b01 = pack2(b.x, b.y);
            unsigned long long b23 = pack2(b.z, b.w);
#pragma unroll
            for (int n = 0; n < NPW; n++) {
                acc[n * 8 + g * 2]     = b01;
                acc[n * 8 + g * 2 + 1] = b23;
            }
        }
    }

    const float4* Wo4 = (const float4*)(Wo + l * F_DIM * L_DIM);

    // prologue: chunk 0 -> buffer 0
    {
        float4* dst = (float4*)Wos[0];
        for (int i = t; i < 2048; i += FB_THREADS) cp_async16(dst + i, Wo4 + i);
        CP_COMMIT();
    }

    for (int kc = 0; kc < 8; kc++) {
        int buf = kc & 1;
        if (kc < 7) {
            float4* dst = (float4*)Wos[buf ^ 1];
            const float4* src = Wo4 + (kc + 1) * 2048;
            for (int i = t; i < 2048; i += FB_THREADS) cp_async16(dst + i, src + i);
        }
        CP_COMMIT();
        CP_WAIT1();
        __syncthreads();

        const float4* Wc4 = (const float4*)Wos[buf];
#pragma unroll
        for (int kk = 0; kk < 8; kk++) {
            unsigned long long rk[NPW];
#pragma unroll
            for (int n = 0; n < NPW; n++) {
                float r = rs[(wi * NPW + n) * F_DIM + kc * 8 + kk];
                rk[n] = pack2(r, r);
            }
#pragma unroll
            for (int g = 0; g < 4; g++) {
                float4 wv = Wc4[kk * 256 + wj * 128 + g * 32 + lane];
                unsigned long long w01 = pack2(wv.x, wv.y);
                unsigned long long w23 = pack2(wv.z, wv.w);
#pragma unroll
                for (int n = 0; n < NPW; n++) {
                    fma2(acc[n * 8 + g * 2],     rk[n], w01);
                    fma2(acc[n * 8 + g * 2 + 1], rk[n], w23);
                }
            }
        }
        __syncthreads();   // all reads of buf done before it is overwritten
    }

    // Per-warp partial softmax over this warp's 512-bin slice; overwrite acc with exp(x - mj).
#pragma unroll
    for (int n = 0; n < NPW; n++) {
        float mx = -1e30f;
#pragma unroll
        for (int i = 0; i < 8; i++) {
            float a, b; unpack2(acc[n * 8 + i], a, b);
            mx = fmaxf(mx, fmaxf(a, b));
        }
#pragma unroll
        for (int off = 16; off; off >>= 1)
            mx = fmaxf(mx, __shfl_xor_sync(0xffffffffu, mx, off));
        float sum = 0.0f;
#pragma unroll
        for (int i = 0; i < 8; i++) {
            float a, b; unpack2(acc[n * 8 + i], a, b);
            a = __expf(a - mx); b = __expf(b - mx);
            sum += a + b;
            acc[n * 8 + i] = pack2(a, b);
        }
#pragma unroll
        for (int off = 16; off; off >>= 1)
            sum += __shfl_xor_sync(0xffffffffu, sum, off);
        if (lane == 0) {
            pm[wi * NPW + n][wj] = mx;
            ps[wi * NPW + n][wj] = sum;
        }
    }
    __syncthreads();

    // Combine across the two bin-groups and accumulate probabilities.
    unsigned long long pacc[8];
#pragma unroll
    for (int i = 0; i < 8; i++) pacc[i] = 0ull;

#pragma unroll
    for (int n = 0; n < NPW; n++) {
        int nb = wi * NPW + n;
        float m0 = pm[nb][0], m1 = pm[nb][1];
        float m = fmaxf(m0, m1);
        float s = ps[nb][0] * __expf(m0 - m) + ps[nb][1] * __expf(m1 - m);
        float mj = (wj == 0) ? m0 : m1;
        float scale = (nodeBase + n < N_NODES) ? (__expf(mj - m) / s) : 0.0f;
        unsigned long long sc2 = pack2(scale, scale);
#pragma unroll
        for (int i = 0; i < 8; i++) fma2(pacc[i], acc[n * 8 + i], sc2);
    }

#pragma unroll
    for (int i = 0; i < 8; i++) {
        float a, b; unpack2(pacc[i], a, b);
        int g = i >> 1, h = i & 1;
        int base = wj * 512 + g * 128 + lane * 4 + 2 * h;
        atomicAdd(&fpart[base],     a);
        atomicAdd(&fpart[base + 1], b);
    }
    __syncthreads();
    if (t < 256) red_add_v4(g_f + t * 4, ((float4*)fpart)[t]);
}

// out = log_softmax(f @ Wcl + bcl)
__global__ void classify_kernel(const float* __restrict__ Wcl,
                                const float* __restrict__ bcl, float* __restrict__ out) {
    int t = threadIdx.x;
    int lane = t & 31, w = t >> 5;
    float loc[N_CLASS];
#pragma unroll
    for (int c = 0; c < N_CLASS; c++) loc[c] = 0.0f;
    for (int i = t; i < L_DIM; i += 256) {
        float fv = g_f[i];
#pragma unroll
        for (int c = 0; c < N_CLASS; c++) loc[c] += fv * Wcl[i * N_CLASS + c];
    }
#pragma unroll
    for (int c = 0; c < N_CLASS; c++)
#pragma unroll
        for (int off = 16; off; off >>= 1)
            loc[c] += __shfl_xor_sync(0xffffffffu, loc[c], off);

    __shared__ float ws[8][N_CLASS];
    if (lane == 0)
#pragma unroll
        for (int c = 0; c < N_CLASS; c++) ws[w][c] = loc[c];
    __syncthreads();
    if (t == 0) {
        float z[N_CLASS];
#pragma unroll
        for (int c = 0; c < N_CLASS; c++) {
            z[c] = bcl[c];
            for (int k = 0; k < 8; k++) z[c] += ws[k][c];
        }
        float m = z[0];
#pragma unroll
        for (int c = 1; c < N_CLASS; c++) m = fmaxf(m, z[c]);
        float s = 0.0f;
#pragma unroll
        for (int c = 0; c < N_CLASS; c++) s += __expf(z[c] - m);
        float ls = logf(s);
#pragma unroll
        for (int c = 0; c < N_CLASS; c++) out[c] = z[c] - m - ls;
    }
}

extern "C" void kernel_launch(void* const* d_in, const int* in_sizes, int n_in,
                              void* d_out, int out_size) {
    const int*   nf   = (const int*)  d_in[0];
    const int*   esrc = (const int*)  d_in[1];
    const int*   edst = (const int*)  d_in[2];
    const float* emb  = (const float*)d_in[3];
    const float* Wh   = (const float*)d_in[4];
    const float* bh   = (const float*)d_in[5];
    const float* Wo   = (const float*)d_in[6];
    const float* bo   = (const float*)d_in[7];
    const float* Wcl  = (const float*)d_in[8];
    const float* bcl  = (const float*)d_in[9];
    float* out = (float*)d_out;

    gather_init<<<(N_NODES * 16 + 255) / 256, 256>>>(nf, emb);
    for (int l = 0; l < R_ROUNDS; l++) {
        scatter_kernel<<<(N_EDGES * 16 + 255) / 256, 256>>>(esrc, edst);
        gemm1_kernel<<<(N_NODES + 255) / 256, 256>>>(Wh, bh, l);
        fused_kernel<<<(N_NODES + NPB - 1) / NPB, FB_THREADS>>>(Wo, bo, l);
    }
    classify_kernel<<<1, 256>>>(Wcl, bcl, out);
}

// round 5
// speedup vs baseline: 1.1113x; 1.1113x over previous
#include <cuda_runtime.h>
#include <math.h>

#define N_NODES  50000
#define N_EDGES  800000
#define F_DIM    64
#define L_DIM    1024
#define R_ROUNDS 3
#define N_CLASS  10

#define FB_THREADS 384        // 12 warps = 6 node-groups x 2 bin-groups
#define NPW      8            // nodes per warp
#define NPB      48           // nodes per block

// Scratch (device globals — no allocation allowed)
__device__ float g_e[N_NODES * F_DIM];   // current embeddings (r after gemm1)
__device__ float g_v[N_NODES * F_DIM];   // v = e + scatter-sum
__device__ float g_f[L_DIM];             // fingerprint accumulator

__device__ __forceinline__ void red_add_v4(float* p, float4 v) {
    asm volatile("red.global.add.v4.f32 [%0], {%1,%2,%3,%4};"
                 :: "l"(p), "f"(v.x), "f"(v.y), "f"(v.z), "f"(v.w) : "memory");
}
__device__ __forceinline__ unsigned long long pack2(float a, float b) {
    unsigned long long r;
    asm("mov.b64 %0, {%1,%2};" : "=l"(r) : "f"(a), "f"(b));
    return r;
}
__device__ __forceinline__ void unpack2(unsigned long long v, float& a, float& b) {
    asm("mov.b64 {%0,%1}, %2;" : "=f"(a), "=f"(b) : "l"(v));
}
__device__ __forceinline__ void fma2(unsigned long long& d,
                                     unsigned long long a, unsigned long long b) {
    asm("fma.rn.f32x2 %0, %1, %2, %0;" : "+l"(d) : "l"(a), "l"(b));
}

// e = emb[node_feature]; v = e; f = 0
__global__ void gather_init(const int* __restrict__ nf, const float* __restrict__ emb) {
    int tid = blockIdx.x * blockDim.x + threadIdx.x;
    if (tid < L_DIM) g_f[tid] = 0.0f;
    if (tid >= N_NODES * 16) return;
    int node = tid >> 4;
    int c    = tid & 15;
    int ft = nf[node];
    float4 val = ((const float4*)emb)[ft * 16 + c];
    ((float4*)g_e)[node * 16 + c] = val;
    ((float4*)g_v)[node * 16 + c] = val;
}

// v[dst] += e[src] for every edge (vector atomics, 16 threads/edge)
__global__ void scatter_kernel(const int* __restrict__ src, const int* __restrict__ dst) {
    int tid = blockIdx.x * blockDim.x + threadIdx.x;
    if (tid >= N_EDGES * 16) return;
    int e = tid >> 4;
    int c = tid & 15;
    int s = __ldg(src + e);
    int d = __ldg(dst + e);
    float4 val = ((const float4*)g_e)[s * 16 + c];
    red_add_v4(g_v + d * 64 + c * 4, val);
}

// r = relu(v @ Wh[l] + bh[l]); write r into BOTH g_e and g_v (v-init for next round)
__global__ void __launch_bounds__(256) gemm1_kernel(const float* __restrict__ Wh,
                                                    const float* __restrict__ bh, int l) {
    __shared__ __align__(16) float Whs[F_DIM * F_DIM];
    __shared__ __align__(16) float bhs[F_DIM];
    int t = threadIdx.x;
    {
        const float4* W4 = (const float4*)(Wh + l * F_DIM * F_DIM);
        float4* Ws4 = (float4*)Whs;
        for (int i = t; i < F_DIM * F_DIM / 4; i += 256) Ws4[i] = W4[i];
        if (t < F_DIM) bhs[t] = bh[l * F_DIM + t];
    }
    __syncthreads();
    int node = blockIdx.x * 256 + t;
    if (node >= N_NODES) return;

    unsigned long long acc2[32];
#pragma unroll
    for (int j2 = 0; j2 < 32; j2++) acc2[j2] = ((const unsigned long long*)bhs)[j2];

    const float4* v4 = ((const float4*)g_v) + node * 16;
    const float4* W4 = (const float4*)Whs;
#pragma unroll
    for (int k4 = 0; k4 < 16; k4++) {
        float4 vv = v4[k4];
        float s[4] = {vv.x, vv.y, vv.z, vv.w};
#pragma unroll
        for (int q = 0; q < 4; q++) {
            unsigned long long a = pack2(s[q], s[q]);
            int k = k4 * 4 + q;
#pragma unroll
            for (int j4 = 0; j4 < 16; j4++) {
                float4 wv = W4[k * 16 + j4];
                fma2(acc2[j4 * 2],     a, pack2(wv.x, wv.y));
                fma2(acc2[j4 * 2 + 1], a, pack2(wv.z, wv.w));
            }
        }
    }
    float4* e4 = ((float4*)g_e) + node * 16;
    float4* w4 = ((float4*)g_v) + node * 16;
#pragma unroll
    for (int j4 = 0; j4 < 16; j4++) {
        float a, b, c, d;
        unpack2(acc2[j4 * 2],     a, b);
        unpack2(acc2[j4 * 2 + 1], c, d);
        float4 o;
        o.x = fmaxf(a, 0.0f); o.y = fmaxf(b, 0.0f);
        o.z = fmaxf(c, 0.0f); o.w = fmaxf(d, 0.0f);
        e4[j4] = o;
        w4[j4] = o;
    }
}

// Fused GEMM2 + softmax + fingerprint accumulation.
// 12 warps = 6 node-groups (wi) x 2 bin-groups (wj).
// Warp (wi,wj): 8 nodes x 512 bins. acc[n*8+g*2+h] = bins wj*512+g*128+lane*4+{2h,2h+1}.
// Wo streamed through smem in 16-row chunks (plain float4 loads, as in R3);
// per-warp partial softmax combined across the two bin-groups online.
__global__ void __launch_bounds__(FB_THREADS, 1)
fused_kernel(const float* __restrict__ Wo, const float* __restrict__ bo, int l) {
    __shared__ __align__(16) float Wos[16 * L_DIM];     // 64 KB
    __shared__ __align__(16) float rs[NPB * F_DIM];     // 12 KB
    __shared__ __align__(16) float fpart[L_DIM];        // 4 KB
    __shared__ float pm[NPB][2];                        // partial max
    __shared__ float ps[NPB][2];                        // partial sumexp

    int t = threadIdx.x;
    int w = t >> 5;
    int lane = t & 31;
    int wj = w & 1;        // bin group
    int wi = w >> 1;       // node group
    int nodeBase = blockIdx.x * NPB + wi * NPW;

    for (int i = t; i < L_DIM; i += FB_THREADS) fpart[i] = 0.0f;
    {
        const float4* e4 = (const float4*)g_e;
        float4* rs4 = (float4*)rs;
        for (int i = t; i < NPB * 16; i += FB_THREADS) {
            int node = blockIdx.x * NPB + (i >> 4);
            if (node < N_NODES) rs4[i] = e4[node * 16 + (i & 15)];
            else                rs4[i] = make_float4(0.f, 0.f, 0.f, 0.f);
        }
    }

    unsigned long long acc[NPW * 8];
    {
        const float4* bo4 = (const float4*)(bo + l * L_DIM);
#pragma unroll
        for (int g = 0; g < 4; g++) {
            float4 b = bo4[wj * 128 + g * 32 + lane];
            unsigned long long b01 = pack2(b.x, b.y);
            unsigned long long b23 = pack2(b.z, b.w);
#pragma unroll
            for (int n = 0; n < NPW; n++) {
                acc[n * 8 + g * 2]     = b01;
                acc[n * 8 + g * 2 + 1] = b23;
            }
        }
    }

    const float4* Wo4 = (const float4*)(Wo + l * F_DIM * L_DIM);
    float4* Wos4 = (float4*)Wos;

    for (int kc = 0; kc < 4; kc++) {
        __syncthreads();
        for (int i = t; i < 4096; i += FB_THREADS) Wos4[i] = Wo4[kc * 4096 + i];
        __syncthreads();
#pragma unroll
        for (int kk = 0; kk < 16; kk++) {
            unsigned long long rk[NPW];
#pragma unroll
            for (int n = 0; n < NPW; n++) {
                float r = rs[(wi * NPW + n) * F_DIM + kc * 16 + kk];
                rk[n] = pack2(r, r);
            }
#pragma unroll
            for (int g = 0; g < 4; g++) {
                float4 wv = Wos4[kk * 256 + wj * 128 + g * 32 + lane];
                unsigned long long w01 = pack2(wv.x, wv.y);
                unsigned long long w23 = pack2(wv.z, wv.w);
#pragma unroll
                for (int n = 0; n < NPW; n++) {
                    fma2(acc[n * 8 + g * 2],     rk[n], w01);
                    fma2(acc[n * 8 + g * 2 + 1], rk[n], w23);
                }
            }
        }
    }

    // Per-warp partial softmax over this warp's 512-bin slice; overwrite acc with exp(x - mj).
#pragma unroll
    for (int n = 0; n < NPW; n++) {
        float mx = -1e30f;
#pragma unroll
        for (int i = 0; i < 8; i++) {
            float a, b; unpack2(acc[n * 8 + i], a, b);
            mx = fmaxf(mx, fmaxf(a, b));
        }
#pragma unroll
        for (int off = 16; off; off >>= 1)
            mx = fmaxf(mx, __shfl_xor_sync(0xffffffffu, mx, off));
        float sum = 0.0f;
#pragma unroll
        for (int i = 0; i < 8; i++) {
            float a, b; unpack2(acc[n * 8 + i], a, b);
            a = __expf(a - mx); b = __expf(b - mx);
            sum += a + b;
            acc[n * 8 + i] = pack2(a, b);
        }
#pragma unroll
        for (int off = 16; off; off >>= 1)
            sum += __shfl_xor_sync(0xffffffffu, sum, off);
        if (lane == 0) {
            pm[wi * NPW + n][wj] = mx;
            ps[wi * NPW + n][wj] = sum;
        }
    }
    __syncthreads();

    // Combine across the two bin-groups and accumulate probabilities.
    unsigned long long pacc[8];
#pragma unroll
    for (int i = 0; i < 8; i++) pacc[i] = 0ull;

#pragma unroll
    for (int n = 0; n < NPW; n++) {
        int nb = wi * NPW + n;
        float m0 = pm[nb][0], m1 = pm[nb][1];
        float m = fmaxf(m0, m1);
        float s = ps[nb][0] * __expf(m0 - m) + ps[nb][1] * __expf(m1 - m);
        float mj = (wj == 0) ? m0 : m1;
        float scale = (nodeBase + n < N_NODES) ? (__expf(mj - m) / s) : 0.0f;
        unsigned long long sc2 = pack2(scale, scale);
#pragma unroll
        for (int i = 0; i < 8; i++) fma2(pacc[i], acc[n * 8 + i], sc2);
    }

#pragma unroll
    for (int i = 0; i < 8; i++) {
        float a, b; unpack2(pacc[i], a, b);
        int g = i >> 1, h = i & 1;
        int base = wj * 512 + g * 128 + lane * 4 + 2 * h;
        atomicAdd(&fpart[base],     a);
        atomicAdd(&fpart[base + 1], b);
    }
    __syncthreads();
    if (t < 256) red_add_v4(g_f + t * 4, ((float4*)fpart)[t]);
}

// out = log_softmax(f @ Wcl + bcl)
__global__ void classify_kernel(const float* __restrict__ Wcl,
                                const float* __restrict__ bcl, float* __restrict__ out) {
    int t = threadIdx.x;
    int lane = t & 31, w = t >> 5;
    float loc[N_CLASS];
#pragma unroll
    for (int c = 0; c < N_CLASS; c++) loc[c] = 0.0f;
    for (int i = t; i < L_DIM; i += 256) {
        float fv = g_f[i];
#pragma unroll
        for (int c = 0; c < N_CLASS; c++) loc[c] += fv * Wcl[i * N_CLASS + c];
    }
#pragma unroll
    for (int c = 0; c < N_CLASS; c++)
#pragma unroll
        for (int off = 16; off; off >>= 1)
            loc[c] += __shfl_xor_sync(0xffffffffu, loc[c], off);

    __shared__ float ws[8][N_CLASS];
    if (lane == 0)
#pragma unroll
        for (int c = 0; c < N_CLASS; c++) ws[w][c] = loc[c];
    __syncthreads();
    if (t == 0) {
        float z[N_CLASS];
#pragma unroll
        for (int c = 0; c < N_CLASS; c++) {
            z[c] = bcl[c];
            for (int k = 0; k < 8; k++) z[c] += ws[k][c];
        }
        float m = z[0];
#pragma unroll
        for (int c = 1; c < N_CLASS; c++) m = fmaxf(m, z[c]);
        float s = 0.0f;
#pragma unroll
        for (int c = 0; c < N_CLASS; c++) s += __expf(z[c] - m);
        float ls = logf(s);
#pragma unroll
        for (int c = 0; c < N_CLASS; c++) out[c] = z[c] - m - ls;
    }
}

extern "C" void kernel_launch(void* const* d_in, const int* in_sizes, int n_in,
                              void* d_out, int out_size) {
    const int*   nf   = (const int*)  d_in[0];
    const int*   esrc = (const int*)  d_in[1];
    const int*   edst = (const int*)  d_in[2];
    const float* emb  = (const float*)d_in[3];
    const float* Wh   = (const float*)d_in[4];
    const float* bh   = (const float*)d_in[5];
    const float* Wo   = (const float*)d_in[6];
    const float* bo   = (const float*)d_in[7];
    const float* Wcl  = (const float*)d_in[8];
    const float* bcl  = (const float*)d_in[9];
    float* out = (float*)d_out;

    gather_init<<<(N_NODES * 16 + 255) / 256, 256>>>(nf, emb);
    for (int l = 0; l < R_ROUNDS; l++) {
        scatter_kernel<<<(N_EDGES * 16 + 255) / 256, 256>>>(esrc, edst);
        gemm1_kernel<<<(N_NODES + 255) / 256, 256>>>(Wh, bh, l);
        fused_kernel<<<(N_NODES + NPB - 1) / NPB, FB_THREADS>>>(Wo, bo, l);
    }
    classify_kernel<<<1, 256>>>(Wcl, bcl, out);
}